// round 3
// baseline (speedup 1.0000x reference)
#include <cuda_runtime.h>

#define NB_B 256      // batch
#define NL   500      // sequence length
#define ND   3        // dihedral dim
#define NC   32       // condition dim
#define NI   35       // per-step input dim (ND+NC)
#define NH   512      // hidden
#define NM   5        // mixtures
#define NO   15       // D*M
#define NOUT 35       // 2*NO + NM
#define NG   36       // number of L-chunks
#define LCHUNK 14     // chunk length (36*14 = 504 >= 500)
#define BTILE 64      // batch tile per block
#define SA_STR 520    // padded smem stride for relu(a) snapshot

// scratch: per-chunk sums / exclusive chunk prefixes of c over l
__device__ float g_S[NG * NB_B * NH];

// -------------------------------------------------------------------------
// K1: per-chunk sums  S[g][b][h] = sum_{l in chunk g} sum_i x[l][b][i] W[l][i][h]
// grid (NG, 4), 512 threads. Accumulator kept fully in registers (8b x 8h per thread).
// -------------------------------------------------------------------------
__global__ __launch_bounds__(512, 1)
void k_chunksum(const float* __restrict__ inputs, const float* __restrict__ z,
                const float* __restrict__ W_enc)
{
    extern __shared__ float sm[];
    float* xs = sm;               // BTILE*NI = 2240 floats
    float* ws = sm + BTILE * NI;  // NI*NH  = 17920 floats

    const int g  = blockIdx.x, bt = blockIdx.y;
    const int b0 = bt * BTILE;
    const int l0 = g * LCHUNK;
    const int l1 = min(l0 + LCHUNK, NL);
    const int tid = threadIdx.x, lane = tid & 31, warp = tid >> 5;
    const int bq = warp >> 1;            // 0..7 : owns b = b0 + bq*8 + bb
    const int hh = (warp & 1) * 256;     // h half: h = hh + j*32 + lane

    float acc[8][8];
#pragma unroll
    for (int a = 0; a < 8; a++)
#pragma unroll
        for (int b = 0; b < 8; b++) acc[a][b] = 0.f;

    for (int l = l0; l < l1; l++) {
        __syncthreads();
        for (int idx = tid; idx < BTILE * NI; idx += 512) {
            int bb = idx / NI, i = idx % NI;
            int gb = b0 + bb;
            xs[idx] = (i < ND)
                ? inputs[(size_t)gb * NL * ND + (size_t)l * ND + i]
                : z[(size_t)gb * NL * NC + (size_t)l * NC + (i - ND)];
        }
        const float4* wsrc = (const float4*)(W_enc + (size_t)l * NI * NH);
        float4* wdst = (float4*)ws;
        for (int idx = tid; idx < NI * NH / 4; idx += 512) wdst[idx] = wsrc[idx];
        __syncthreads();

#pragma unroll 1
        for (int i = 0; i < NI; i++) {
            float xv[8], wv[8];
#pragma unroll
            for (int bb = 0; bb < 8; bb++) xv[bb] = xs[(bq * 8 + bb) * NI + i];
#pragma unroll
            for (int j = 0; j < 8; j++) wv[j] = ws[i * NH + hh + j * 32 + lane];
#pragma unroll
            for (int bb = 0; bb < 8; bb++)
#pragma unroll
                for (int j = 0; j < 8; j++) acc[bb][j] += xv[bb] * wv[j];
        }
    }

    const size_t base = (size_t)g * NB_B * NH;
#pragma unroll
    for (int bb = 0; bb < 8; bb++)
#pragma unroll
        for (int j = 0; j < 8; j++)
            g_S[base + (size_t)(b0 + bq * 8 + bb) * NH + hh + j * 32 + lane] = acc[bb][j];
}

// -------------------------------------------------------------------------
// K2: in-place exclusive scan over chunks per (b,h), folding in b_enc.
// After this, g_S[g][b][h] = b_enc[h] + sum_{l < g*LCHUNK} c[l][b][h]
// -------------------------------------------------------------------------
__global__ void k_scan(const float* __restrict__ b_enc)
{
    const int idx = blockIdx.x * 512 + threadIdx.x;  // < NB_B*NH
    const int h = idx & (NH - 1);
    float run = b_enc[h];
#pragma unroll 1
    for (int g = 0; g < NG; g++) {
        size_t off = (size_t)g * NB_B * NH + idx;
        float v = g_S[off];
        g_S[off] = run;
        run += v;
    }
}

// -------------------------------------------------------------------------
// K3: per chunk: recompute c[l], maintain running a (in regs), per step:
//   h = relu(a) -> smem snapshot -> project to 35 outputs (mu|sigma|pi) -> a += c[l]
// grid (NG, 4), 512 threads, ~216 KB dynamic smem, 1 CTA/SM.
// -------------------------------------------------------------------------
__global__ __launch_bounds__(512, 1)
void k_main(const float* __restrict__ inputs, const float* __restrict__ z,
            const float* __restrict__ W_enc,
            const float* __restrict__ V_mu, const float* __restrict__ b_mu,
            const float* __restrict__ V_sigma, const float* __restrict__ b_sigma,
            const float* __restrict__ V_pi, const float* __restrict__ b_pi,
            float* __restrict__ out)
{
    extern __shared__ float sm[];
    float* sa  = sm;                              // BTILE*SA_STR = 33280 (relu snapshot)
    float* buf = sa + BTILE * SA_STR;             // 512*36 = 18432 (shared V / W stage)
    float* xs  = buf + NH * 36;                   // 2240
    float* bs  = xs + BTILE * NI;                 // 64 (bias, padded)

    const int g  = blockIdx.x, bt = blockIdx.y;
    const int b0 = bt * BTILE;
    const int l0 = g * LCHUNK;
    const int l1 = min(l0 + LCHUNK, NL);
    const int tid = threadIdx.x, lane = tid & 31, warp = tid >> 5;
    const int bq = warp >> 1;
    const int hh = (warp & 1) * 256;
    // projection mapping
    const int pb = tid >> 3;       // 0..63 batch row
    const int og = tid & 7;        // o in {og, og+8, og+16, og+24, (og+32 if og<3)}

    // init running accumulator from chunk base (b_enc already folded in)
    float acc[8][8];
    {
        const size_t base = (size_t)g * NB_B * NH;
#pragma unroll
        for (int bb = 0; bb < 8; bb++)
#pragma unroll
            for (int j = 0; j < 8; j++)
                acc[bb][j] = g_S[base + (size_t)(b0 + bq * 8 + bb) * NH + hh + j * 32 + lane];
    }

    for (int l = l0; l < l1; l++) {
        __syncthreads();  // prev stage A done with buf/xs; prev stage B done with sa

        // snapshot h = relu(a) into smem (pre-update: exclusive prefix semantics)
#pragma unroll
        for (int bb = 0; bb < 8; bb++)
#pragma unroll
            for (int j = 0; j < 8; j++)
                sa[(bq * 8 + bb) * SA_STR + hh + j * 32 + lane] = fmaxf(acc[bb][j], 0.f);

        // stage Vcat[l] into buf: layout [h][36], cols 0..34 = mu|sigma|pi
        for (int idx = tid; idx < NH * NOUT; idx += 512) {
            int h = idx / NOUT, o = idx % NOUT;
            float v;
            if (o < NO)            v = V_mu   [(size_t)l * NH * NO + (size_t)h * NO + o];
            else if (o < 2 * NO)   v = V_sigma[(size_t)l * NH * NO + (size_t)h * NO + (o - NO)];
            else                   v = V_pi   [(size_t)l * NH * NM + (size_t)h * NM + (o - 2 * NO)];
            buf[h * 36 + o] = v;
        }
        if (tid < NOUT) {
            int o = tid;
            bs[o] = (o < NO) ? b_mu[(size_t)l * NO + o]
                  : (o < 2 * NO) ? b_sigma[(size_t)l * NO + (o - NO)]
                  : b_pi[(size_t)l * NM + (o - 2 * NO)];
        }
        // stage x[l] (needed by stage A below)
        for (int idx = tid; idx < BTILE * NI; idx += 512) {
            int bb = idx / NI, i = idx % NI;
            int gb = b0 + bb;
            xs[idx] = (i < ND)
                ? inputs[(size_t)gb * NL * ND + (size_t)l * ND + i]
                : z[(size_t)gb * NL * NC + (size_t)l * NC + (i - ND)];
        }
        __syncthreads();

        // ---- stage B: out[b][l][:] = relu(a) @ Vcat[l] + bias ----
        {
            float a0 = bs[og], a1 = bs[og + 8], a2 = bs[og + 16], a3 = bs[og + 24];
            float a4 = (og < 3) ? bs[og + 32] : 0.f;
#pragma unroll 4
            for (int h = 0; h < NH; h++) {
                float av = sa[pb * SA_STR + h];
                const float* vr = &buf[h * 36 + og];
                a0 += av * vr[0];
                a1 += av * vr[8];
                a2 += av * vr[16];
                a3 += av * vr[24];
                if (og < 3) a4 += av * vr[32];
            }
            const size_t ob = (size_t)(b0 + pb) * NL * NOUT + (size_t)l * NOUT + og;
            out[ob]      = a0;
            out[ob + 8]  = a1;
            out[ob + 16] = a2;
            out[ob + 24] = a3;
            if (og < 3) out[ob + 32] = a4;
        }
        __syncthreads();

        // ---- stage A: a += c[l]  (skip for last step of chunk: dead value) ----
        if (l + 1 < l1) {
            const float4* wsrc = (const float4*)(W_enc + (size_t)l * NI * NH);
            for (int idx = tid; idx < NI * NH / 4; idx += 512)
                ((float4*)buf)[idx] = wsrc[idx];
            __syncthreads();
#pragma unroll 1
            for (int i = 0; i < NI; i++) {
                float xv[8], wv[8];
#pragma unroll
                for (int bb = 0; bb < 8; bb++) xv[bb] = xs[(bq * 8 + bb) * NI + i];
#pragma unroll
                for (int j = 0; j < 8; j++) wv[j] = buf[i * NH + hh + j * 32 + lane];
#pragma unroll
                for (int bb = 0; bb < 8; bb++)
#pragma unroll
                    for (int j = 0; j < 8; j++) acc[bb][j] += xv[bb] * wv[j];
            }
        }
    }
}

// -------------------------------------------------------------------------
extern "C" void kernel_launch(void* const* d_in, const int* in_sizes, int n_in,
                              void* d_out, int out_size)
{
    const float* inputs  = (const float*)d_in[0];
    const float* z       = (const float*)d_in[1];
    const float* W_enc   = (const float*)d_in[2];
    const float* b_enc   = (const float*)d_in[3];
    const float* V_mu    = (const float*)d_in[4];
    const float* b_mu    = (const float*)d_in[5];
    const float* V_sigma = (const float*)d_in[6];
    const float* b_sigma = (const float*)d_in[7];
    const float* V_pi    = (const float*)d_in[8];
    const float* b_pi    = (const float*)d_in[9];
    float* out = (float*)d_out;

    const int SMEM_K1 = (BTILE * NI + NI * NH) * 4;                        // 80,640 B
    const int SMEM_K3 = (BTILE * SA_STR + NH * 36 + BTILE * NI + 64) * 4;  // 216,064 B

    cudaFuncSetAttribute(k_chunksum, cudaFuncAttributeMaxDynamicSharedMemorySize, SMEM_K1);
    cudaFuncSetAttribute(k_main,     cudaFuncAttributeMaxDynamicSharedMemorySize, SMEM_K3);

    k_chunksum<<<dim3(NG, NB_B / BTILE), 512, SMEM_K1>>>(inputs, z, W_enc);
    k_scan<<<(NB_B * NH) / 512, 512>>>(b_enc);
    k_main<<<dim3(NG, NB_B / BTILE), 512, SMEM_K3>>>(
        inputs, z, W_enc, V_mu, b_mu, V_sigma, b_sigma, V_pi, b_pi, out);
}

// round 6
// speedup vs baseline: 1.2786x; 1.2786x over previous
#include <cuda_runtime.h>
#include <cstdint>

#define NB   256     // batch
#define NL   500     // sequence length
#define ND   3       // dihedral dim
#define NC   32      // condition dim
#define NI   35      // per-step input dim
#define KP   40      // K padded to multiple of 8 for mma
#define NH   512     // hidden
#define NM   5
#define NO   15
#define NOUT 35      // 2*NO + NM
#define NP   40      // output cols padded to multiple of 8
#define NG   36      // L-chunks
#define LCH  14      // chunk length (36*14 = 504 >= 500)
#define BT   64      // batch tile per block
#define XS_STR 44    // x smem stride  (== 12 mod 32 -> conflict-free A frags)
#define WS_STR 520   // W smem stride  (==  8 mod 32 -> conflict-free B frags)
#define SA_STR 516   // a smem stride  (==  4 mod 32 -> conflict-free A frags)

// scratch: per-chunk sums / exclusive chunk prefixes of c over l
__device__ float g_S[NG * NB * NH];

// ---------------- helpers ----------------
__device__ __forceinline__ float tf32r(float x) {
    uint32_t u; asm("cvt.rna.tf32.f32 %0, %1;" : "=r"(u) : "f"(x));
    return __uint_as_float(u);
}
__device__ __forceinline__ uint32_t tf32u(float x) {
    uint32_t u; asm("cvt.rna.tf32.f32 %0, %1;" : "=r"(u) : "f"(x));
    return u;
}
// D += A@B, m16n8k8 tf32. C/D f32.
__device__ __forceinline__ void mma8(float* c, const uint32_t* a, uint32_t b0, uint32_t b1) {
    asm volatile("mma.sync.aligned.m16n8k8.row.col.f32.tf32.tf32.f32 "
        "{%0,%1,%2,%3}, {%4,%5,%6,%7}, {%8,%9}, {%0,%1,%2,%3};"
        : "+f"(c[0]), "+f"(c[1]), "+f"(c[2]), "+f"(c[3])
        : "r"(a[0]), "r"(a[1]), "r"(a[2]), "r"(a[3]), "r"(b0), "r"(b1));
}

// stage x[l] (tf32-converted, zero-padded K 35->40) into xs[BT][XS_STR]
__device__ __forceinline__ void stage_x(float* xs, const float* __restrict__ inputs,
                                        const float* __restrict__ z, int b0, int l, int tid) {
    for (int idx = tid; idx < BT * KP; idx += 512) {
        int b = idx / KP, k = idx - b * KP;
        int gb = b0 + b;
        float v = 0.f;
        if (k < ND)      v = inputs[((size_t)gb * NL + l) * ND + k];
        else if (k < NI) v = z[((size_t)gb * NL + l) * NC + (k - ND)];
        xs[b * XS_STR + k] = tf32r(v);
    }
}
// stage W_enc[l] (tf32, zero-padded rows) into ws[KP][WS_STR]
__device__ __forceinline__ void stage_w(float* ws, const float* __restrict__ W_enc,
                                        int l, int tid) {
    const float4* src = (const float4*)(W_enc + (size_t)l * NI * NH);
    for (int idx = tid; idx < KP * (NH / 4); idx += 512) {
        int k = idx >> 7, h4 = idx & 127;
        float4 v = make_float4(0.f, 0.f, 0.f, 0.f);
        if (k < NI) v = src[k * (NH / 4) + h4];
        v.x = tf32r(v.x); v.y = tf32r(v.y); v.z = tf32r(v.z); v.w = tf32r(v.w);
        *(float4*)(ws + k * WS_STR + h4 * 4) = v;
    }
}
// A fragments (m16 x k40) for rows [mrow0, mrow0+16)
__device__ __forceinline__ void load_afrag_x(uint32_t a[5][4], const float* xs,
                                             int mrow0, int gid, int tig) {
    const float* p = xs + (mrow0 + gid) * XS_STR + tig;
#pragma unroll
    for (int s = 0; s < 5; s++) {
        a[s][0] = __float_as_uint(p[s * 8]);
        a[s][1] = __float_as_uint(p[8 * XS_STR + s * 8]);
        a[s][2] = __float_as_uint(p[s * 8 + 4]);
        a[s][3] = __float_as_uint(p[8 * XS_STR + s * 8 + 4]);
    }
}

// -------------------------------------------------------------------------
// K1: per-chunk sums S[g][b][h] via tf32 mma, accumulators in registers.
// grid (NG, 4), 512 threads (16 warps = 4 m-groups x 4 n-groups).
// -------------------------------------------------------------------------
__global__ __launch_bounds__(512, 1)
void k_chunksum(const float* __restrict__ inputs, const float* __restrict__ z,
                const float* __restrict__ W_enc)
{
    extern __shared__ float sm[];
    float* xs = sm;                 // 2816
    float* ws = sm + BT * XS_STR;   // 20800

    const int g = blockIdx.x, b0 = blockIdx.y * BT;
    const int l0 = g * LCH, l1 = min(l0 + LCH, NL);
    const int tid = threadIdx.x, lane = tid & 31, warp = tid >> 5;
    const int gid = lane >> 2, tig = lane & 3;
    const int mw = warp & 3, nw = warp >> 2;
    const int mrow0 = mw * 16;

    float acc[16][4];
#pragma unroll
    for (int t = 0; t < 16; t++) { acc[t][0] = acc[t][1] = acc[t][2] = acc[t][3] = 0.f; }

    for (int l = l0; l < l1; l++) {
        __syncthreads();
        stage_x(xs, inputs, z, b0, l, tid);
        stage_w(ws, W_enc, l, tid);
        __syncthreads();
        uint32_t a[5][4];
        load_afrag_x(a, xs, mrow0, gid, tig);
#pragma unroll
        for (int t = 0; t < 16; t++) {
            const float* wp = ws + nw * 128 + t * 8 + gid;
#pragma unroll
            for (int s = 0; s < 5; s++) {
                uint32_t bb0 = __float_as_uint(wp[(s * 8 + tig) * WS_STR]);
                uint32_t bb1 = __float_as_uint(wp[(s * 8 + tig + 4) * WS_STR]);
                mma8(acc[t], a[s], bb0, bb1);
            }
        }
    }

    float* dst = g_S + (size_t)g * NB * NH;
#pragma unroll
    for (int t = 0; t < 16; t++) {
        int col = nw * 128 + t * 8 + 2 * tig;
        int row = b0 + mrow0 + gid;
        dst[(size_t)row * NH + col]           = acc[t][0];
        dst[(size_t)row * NH + col + 1]       = acc[t][1];
        dst[(size_t)(row + 8) * NH + col]     = acc[t][2];
        dst[(size_t)(row + 8) * NH + col + 1] = acc[t][3];
    }
}

// -------------------------------------------------------------------------
// K2: exclusive scan over chunks per (b,h), folding in b_enc.
// -------------------------------------------------------------------------
__global__ void k_scan(const float* __restrict__ b_enc)
{
    const int idx = blockIdx.x * 512 + threadIdx.x;  // < NB*NH
    const int h = idx & (NH - 1);
    float run = b_enc[h];
#pragma unroll 1
    for (int g = 0; g < NG; g++) {
        size_t off = (size_t)g * NB * NH + idx;
        float v = g_S[off];
        g_S[off] = run;
        run += v;
    }
}

// -------------------------------------------------------------------------
// K3: persistent a in smem; per step: stage B (relu(a) @ Vcat, 4-way K-split
// across warps, reduce through dead Vcat smem) then stage A (a += x@W) via mma.
// grid (NG, 4), 512 threads, 226.7KB smem, 1 CTA/SM, 1 wave of 144.
// -------------------------------------------------------------------------
__global__ __launch_bounds__(512, 1)
void k_main(const float* __restrict__ inputs, const float* __restrict__ z,
            const float* __restrict__ W_enc,
            const float* __restrict__ V_mu, const float* __restrict__ b_mu,
            const float* __restrict__ V_sigma, const float* __restrict__ b_sigma,
            const float* __restrict__ V_pi, const float* __restrict__ b_pi,
            float* __restrict__ out)
{
    extern __shared__ float sm[];
    float* sA  = sm;                       // BT*SA_STR = 33024 (persistent a, f32)
    float* buf = sA + BT * SA_STR;         // 20800: Vcat[512][40] / W[40][520] / red 3*2560
    float* xs  = buf + KP * WS_STR;        // 2816
    float* bs  = xs + BT * XS_STR;         // 40

    const int g = blockIdx.x, b0 = blockIdx.y * BT;
    const int l0 = g * LCH, l1 = min(l0 + LCH, NL);
    const int tid = threadIdx.x, lane = tid & 31, warp = tid >> 5;
    const int gid = lane >> 2, tig = lane & 3;
    const int mw = warp & 3;   // m-group (both stages)
    const int qw = warp >> 2;  // stage B: k-group; stage A: n-group
    const int mrow0 = mw * 16;

    // init a from exclusive chunk prefix (b_enc folded in by k_scan)
    {
        const float* src = g_S + (size_t)g * NB * NH + (size_t)b0 * NH;
        for (int idx = tid; idx < BT * NH; idx += 512) {
            int b = idx >> 9, h = idx & (NH - 1);
            sA[b * SA_STR + h] = src[(size_t)b * NH + h];
        }
    }

    for (int l = l0; l < l1; l++) {
        __syncthreads();  // prev stage A done (sA, buf)

        // ---- stage Vcat[l] (tf32) into buf, biases, x[l] ----
        for (int idx = tid; idx < NH * NP; idx += 512) {
            int h = idx / NP, o = idx - h * NP;
            float v = 0.f;
            if (o < NO)          v = V_mu   [((size_t)l * NH + h) * NO + o];
            else if (o < 2 * NO) v = V_sigma[((size_t)l * NH + h) * NO + (o - NO)];
            else if (o < NOUT)   v = V_pi   [((size_t)l * NH + h) * NM + (o - 2 * NO)];
            buf[h * NP + o] = tf32r(v);
        }
        if (tid < NP) {
            int o = tid; float v = 0.f;
            if (o < NO)          v = b_mu[(size_t)l * NO + o];
            else if (o < 2 * NO) v = b_sigma[(size_t)l * NO + (o - NO)];
            else if (o < NOUT)   v = b_pi[(size_t)l * NM + (o - 2 * NO)];
            bs[o] = v;
        }
        stage_x(xs, inputs, z, b0, l, tid);
        __syncthreads();

        // ---- stage B: relu(a) @ Vcat, warps = 4m x 4k (k-range 128 each) ----
        float bacc[5][4];
#pragma unroll
        for (int t = 0; t < 5; t++) { bacc[t][0] = bacc[t][1] = bacc[t][2] = bacc[t][3] = 0.f; }
        {
            const float* ap = sA + (mrow0 + gid) * SA_STR + qw * 128 + tig;
#pragma unroll
            for (int s = 0; s < 16; s++) {
                uint32_t a[4];
                a[0] = tf32u(fmaxf(ap[s * 8], 0.f));
                a[1] = tf32u(fmaxf(ap[8 * SA_STR + s * 8], 0.f));
                a[2] = tf32u(fmaxf(ap[s * 8 + 4], 0.f));
                a[3] = tf32u(fmaxf(ap[8 * SA_STR + s * 8 + 4], 0.f));
                const float* vp = buf + (qw * 128 + s * 8 + tig) * NP + gid;
#pragma unroll
                for (int t = 0; t < 5; t++) {
                    uint32_t bb0 = __float_as_uint(vp[t * 8]);
                    uint32_t bb1 = __float_as_uint(vp[4 * NP + t * 8]);
                    mma8(bacc[t], a, bb0, bb1);
                }
            }
        }
        __syncthreads();  // Vcat reads complete -> buf reusable as reduction scratch

        // k-groups 1..3 spill partials into buf; group 0 keeps its partial in regs
        if (qw != 0) {
            float* red = buf + (qw - 1) * (BT * NP);
#pragma unroll
            for (int t = 0; t < 5; t++) {
                int col = t * 8 + 2 * tig;
                float* r0 = red + (mrow0 + gid) * NP + col;
                r0[0] = bacc[t][0];
                r0[1] = bacc[t][1];
                r0[8 * NP]     = bacc[t][2];
                r0[8 * NP + 1] = bacc[t][3];
            }
        }
        __syncthreads();
        if (qw == 0) {
#pragma unroll
            for (int t = 0; t < 5; t++) {
                int col = t * 8 + 2 * tig;
                int row = mrow0 + gid;
                float v0 = bacc[t][0] + bs[col];
                float v1 = bacc[t][1] + bs[col + 1];
                float v2 = bacc[t][2] + bs[col];
                float v3 = bacc[t][3] + bs[col + 1];
#pragma unroll
                for (int kg = 0; kg < 3; kg++) {
                    const float* r0 = buf + kg * (BT * NP) + row * NP + col;
                    v0 += r0[0]; v1 += r0[1];
                    v2 += r0[8 * NP]; v3 += r0[8 * NP + 1];
                }
                size_t ob  = ((size_t)(b0 + row) * NL + l) * NOUT + col;
                size_t ob2 = ((size_t)(b0 + row + 8) * NL + l) * NOUT + col;
                if (col < NOUT)     { out[ob]     = v0; out[ob2]     = v2; }
                if (col + 1 < NOUT) { out[ob + 1] = v1; out[ob2 + 1] = v3; }
            }
        }

        // ---- stage A: a += x[l] @ W[l]  (dead on last step of chunk) ----
        if (l + 1 < l1) {
            __syncthreads();  // reduction reads done before W overwrites buf
            stage_w(buf, W_enc, l, tid);
            __syncthreads();
            uint32_t a[5][4];
            load_afrag_x(a, xs, mrow0, gid, tig);
#pragma unroll 4
            for (int t = 0; t < 16; t++) {
                int n0 = qw * 128 + t * 8;
                float* cp = sA + (mrow0 + gid) * SA_STR + n0 + 2 * tig;
                float c[4];
                c[0] = cp[0]; c[1] = cp[1];
                c[2] = cp[8 * SA_STR]; c[3] = cp[8 * SA_STR + 1];
                const float* wp = buf + n0 + gid;
#pragma unroll
                for (int s = 0; s < 5; s++) {
                    uint32_t bb0 = __float_as_uint(wp[(s * 8 + tig) * WS_STR]);
                    uint32_t bb1 = __float_as_uint(wp[(s * 8 + tig + 4) * WS_STR]);
                    mma8(c, a[s], bb0, bb1);
                }
                cp[0] = c[0]; cp[1] = c[1];
                cp[8 * SA_STR] = c[2]; cp[8 * SA_STR + 1] = c[3];
            }
        }
    }
}

// -------------------------------------------------------------------------
extern "C" void kernel_launch(void* const* d_in, const int* in_sizes, int n_in,
                              void* d_out, int out_size)
{
    const float* inputs  = (const float*)d_in[0];
    const float* z       = (const float*)d_in[1];
    const float* W_enc   = (const float*)d_in[2];
    const float* b_enc   = (const float*)d_in[3];
    const float* V_mu    = (const float*)d_in[4];
    const float* b_mu    = (const float*)d_in[5];
    const float* V_sigma = (const float*)d_in[6];
    const float* b_sigma = (const float*)d_in[7];
    const float* V_pi    = (const float*)d_in[8];
    const float* b_pi    = (const float*)d_in[9];
    float* out = (float*)d_out;

    const int SMEM_K1 = (BT * XS_STR + KP * WS_STR) * 4;                          //  94,464 B
    const int SMEM_K3 = (BT * SA_STR + KP * WS_STR + BT * XS_STR + NP) * 4;       // 226,720 B

    cudaFuncSetAttribute(k_chunksum, cudaFuncAttributeMaxDynamicSharedMemorySize, SMEM_K1);
    cudaFuncSetAttribute(k_main,     cudaFuncAttributeMaxDynamicSharedMemorySize, SMEM_K3);

    k_chunksum<<<dim3(NG, NB / BT), 512, SMEM_K1>>>(inputs, z, W_enc);
    k_scan<<<(NB * NH) / 512, 512>>>(b_enc);
    k_main<<<dim3(NG, NB / BT), 512, SMEM_K3>>>(
        inputs, z, W_enc, V_mu, b_mu, V_sigma, b_sigma, V_pi, b_pi, out);
}

// round 9
// speedup vs baseline: 2.4187x; 1.8918x over previous
#include <cuda_runtime.h>
#include <cstdint>

#define NB   256
#define NL   500
#define ND   3
#define NC   32
#define NI   35
#define KP   40
#define NH   512
#define NM   5
#define NO   15
#define NOUT 35
#define NP   40
#define NG   36
#define LCH  14
#define BT   64
#define XS_STR 44     // mod 32 = 12 -> conflict-free A frags
#define WS_STR 520    // mod 32 = 8  -> conflict-free B frags
#define SNS    260    // mod 32 = 4  -> conflict-free A frags

#define K1BUF (BT * XS_STR + KP * WS_STR)   // 23616 floats per pipeline slot

// chunk sums -> exclusive chunk prefixes (+b_enc) after k_scan
__device__ float g_S[NG * NB * NH];
// within-chunk inclusive prefixes P[l][b][h] (262MB scratch)
__device__ float g_C[NL * NB * NH];

// ---------------- helpers ----------------
__device__ __forceinline__ float tf32r(float x) {
    uint32_t u; asm("cvt.rna.tf32.f32 %0, %1;" : "=r"(u) : "f"(x));
    return __uint_as_float(u);
}
__device__ __forceinline__ uint32_t tf32u(float x) {
    uint32_t u; asm("cvt.rna.tf32.f32 %0, %1;" : "=r"(u) : "f"(x));
    return u;
}
__device__ __forceinline__ void mma8(float* c, const uint32_t* a, uint32_t b0, uint32_t b1) {
    asm volatile("mma.sync.aligned.m16n8k8.row.col.f32.tf32.tf32.f32 "
        "{%0,%1,%2,%3}, {%4,%5,%6,%7}, {%8,%9}, {%0,%1,%2,%3};"
        : "+f"(c[0]), "+f"(c[1]), "+f"(c[2]), "+f"(c[3])
        : "r"(a[0]), "r"(a[1]), "r"(a[2]), "r"(a[3]), "r"(b0), "r"(b1));
}
__device__ __forceinline__ void cpa4(uint32_t dst, const void* src) {
    asm volatile("cp.async.ca.shared.global [%0], [%1], 4;" :: "r"(dst), "l"(src) : "memory");
}
__device__ __forceinline__ void cpa16(uint32_t dst, const void* src) {
    asm volatile("cp.async.ca.shared.global [%0], [%1], 16;" :: "r"(dst), "l"(src) : "memory");
}
#define CP_COMMIT() asm volatile("cp.async.commit_group;" ::: "memory")
#define CP_WAIT1()  asm volatile("cp.async.wait_group 1;" ::: "memory")

// -------------------------------------------------------------------------
// K1: per step l: acc += x[l]@W[l] (tf32 mma); store P[l]=acc to g_C; at
// chunk end store acc to g_S. Double-buffered cp.async staging of W and x.
// grid (NG, 4), 512 threads.
// -------------------------------------------------------------------------
__global__ __launch_bounds__(512, 1)
void k_chunksum(const float* __restrict__ inputs, const float* __restrict__ z,
                const float* __restrict__ W_enc)
{
    extern __shared__ float sm[];
    const int g = blockIdx.x, b0 = blockIdx.y * BT;
    const int l0 = g * LCH, l1 = min(l0 + LCH, NL);
    const int tid = threadIdx.x, lane = tid & 31, warp = tid >> 5;
    const int gid = lane >> 2, tig = lane & 3;
    const int mw = warp & 3, nw = warp >> 2;
    const int mrow0 = mw * 16;

    // zero pads once (never touched by cp.async)
    for (int s2 = 0; s2 < 2; s2++) {
        float* x = sm + s2 * K1BUF;
        float* w = x + BT * XS_STR;
        for (int i = tid; i < BT * 5; i += 512) x[(i / 5) * XS_STR + 35 + i % 5] = 0.f;
        for (int i = tid; i < 5 * NH; i += 512) w[(35 + i / NH) * WS_STR + (i % NH)] = 0.f;
    }

    // prefetch helper (inlined twice via lambda)
    auto prefetch = [&](int l, int slot) {
        float* x = sm + slot * K1BUF;
        float* w = x + BT * XS_STR;
        uint32_t xb = (uint32_t)__cvta_generic_to_shared(x);
        uint32_t wb = (uint32_t)__cvta_generic_to_shared(w);
        for (int idx = tid; idx < BT * NI; idx += 512) {
            int b = idx / NI, k = idx - b * NI;
            const float* src = (k < ND)
                ? inputs + ((size_t)(b0 + b) * NL + l) * ND + k
                : z + ((size_t)(b0 + b) * NL + l) * NC + (k - ND);
            cpa4(xb + (uint32_t)(b * XS_STR + k) * 4u, src);
        }
        const float* wsrc = W_enc + (size_t)l * NI * NH;
        for (int idx = tid; idx < NI * (NH / 4); idx += 512) {
            int k = idx >> 7, h4 = idx & 127;
            cpa16(wb + (uint32_t)(k * WS_STR + h4 * 4) * 4u, wsrc + k * NH + h4 * 4);
        }
    };

    float acc[16][4];
#pragma unroll
    for (int t = 0; t < 16; t++) { acc[t][0] = acc[t][1] = acc[t][2] = acc[t][3] = 0.f; }

    prefetch(l0, 0); CP_COMMIT();
    if (l0 + 1 < l1) prefetch(l0 + 1, 1);
    CP_COMMIT();

    for (int l = l0; l < l1; l++) {
        const int cur = (l - l0) & 1;
        CP_WAIT1();
        __syncthreads();
        const float* x = sm + cur * K1BUF;
        const float* w = x + BT * XS_STR;

        uint32_t a[5][4];
        {
            const float* p = x + (mrow0 + gid) * XS_STR + tig;
#pragma unroll
            for (int s = 0; s < 5; s++) {
                a[s][0] = tf32u(p[s * 8]);
                a[s][1] = tf32u(p[8 * XS_STR + s * 8]);
                a[s][2] = tf32u(p[s * 8 + 4]);
                a[s][3] = tf32u(p[8 * XS_STR + s * 8 + 4]);
            }
        }
#pragma unroll
        for (int t = 0; t < 16; t++) {
            const float* wp = w + nw * 128 + t * 8 + gid;
#pragma unroll
            for (int s = 0; s < 5; s++) {
                uint32_t bb0 = tf32u(wp[(s * 8 + tig) * WS_STR]);
                uint32_t bb1 = tf32u(wp[(s * 8 + tig + 4) * WS_STR]);
                mma8(acc[t], a[s], bb0, bb1);
            }
        }
        __syncthreads();          // all warps done reading slot `cur`
        if (l + 2 < l1) prefetch(l + 2, cur);
        CP_COMMIT();

        if (l + 1 < l1) {         // store P[l] (not needed for last step of chunk)
            float* d0 = g_C + ((size_t)l * NB + b0 + mrow0 + gid) * NH;
            float* d1 = d0 + 8 * NH;
#pragma unroll
            for (int t = 0; t < 16; t++) {
                int col = nw * 128 + t * 8 + 2 * tig;
                *(float2*)&d0[col] = make_float2(acc[t][0], acc[t][1]);
                *(float2*)&d1[col] = make_float2(acc[t][2], acc[t][3]);
            }
        }
    }

    float* dst = g_S + (size_t)g * NB * NH;
#pragma unroll
    for (int t = 0; t < 16; t++) {
        int col = nw * 128 + t * 8 + 2 * tig;
        int row = b0 + mrow0 + gid;
        *(float2*)&dst[(size_t)row * NH + col]       = make_float2(acc[t][0], acc[t][1]);
        *(float2*)&dst[(size_t)(row + 8) * NH + col] = make_float2(acc[t][2], acc[t][3]);
    }
}

// -------------------------------------------------------------------------
// K2: exclusive scan over chunks per (b,h), folding in b_enc.
// -------------------------------------------------------------------------
__global__ void k_scan(const float* __restrict__ b_enc)
{
    const int idx = blockIdx.x * 512 + threadIdx.x;
    const int h = idx & (NH - 1);
    float run = b_enc[h];
#pragma unroll 1
    for (int g = 0; g < NG; g++) {
        size_t off = (size_t)g * NB * NH + idx;
        float v = g_S[off];
        g_S[off] = run;
        run += v;
    }
}

// -------------------------------------------------------------------------
// K3: per step: snapshot relu(g_S[g] + P[l-1]) in two k-halves -> stage-B mma
// (warps = 4m x 4k within each half) -> reduce -> out. Vcat double-buffered
// via cp.async. grid (NG, 4), 512 threads, 230.7KB smem.
// -------------------------------------------------------------------------
__global__ __launch_bounds__(512, 1)
void k_main(const float* __restrict__ V_mu, const float* __restrict__ b_mu,
            const float* __restrict__ V_sigma, const float* __restrict__ b_sigma,
            const float* __restrict__ V_pi, const float* __restrict__ b_pi,
            float* __restrict__ out)
{
    extern __shared__ float sm[];
    float* snap = sm;                  // 64*260 = 16640 floats (also reduce scratch)
    float* vs   = sm + BT * SNS;       // 2 * 512*40 = 40960
    float* bsm  = vs + 2 * NH * NP;    // 2 * 40

    const int g = blockIdx.x, b0 = blockIdx.y * BT;
    const int l0 = g * LCH, l1 = min(l0 + LCH, NL);
    const int tid = threadIdx.x, lane = tid & 31, warp = tid >> 5;
    const int gid = lane >> 2, tig = lane & 3;
    const int mw = warp & 3, qw = warp >> 2;
    const int mrow0 = mw * 16;
    const int hoff = tid & 255, rpar = tid >> 8;

    // zero pad columns of Vcat buffers and bias pads (never cp.async'd)
    for (int i = tid; i < 2 * NH * 5; i += 512) {
        int bsel = i / (NH * 5), r = i - bsel * NH * 5;
        vs[bsel * NH * NP + (r / 5) * NP + 35 + r % 5] = 0.f;
    }
    if (tid < 10) bsm[(tid / 5) * NP + 35 + tid % 5] = 0.f;

    auto prefetch_v = [&](int l, int slot) {
        uint32_t vb = (uint32_t)__cvta_generic_to_shared(vs + slot * NH * NP);
        for (int idx = tid; idx < NH * NOUT; idx += 512) {
            int h = idx / NOUT, o = idx - h * NOUT;
            const float* src;
            if (o < NO)          src = V_mu    + ((size_t)l * NH + h) * NO + o;
            else if (o < 2 * NO) src = V_sigma + ((size_t)l * NH + h) * NO + (o - NO);
            else                 src = V_pi    + ((size_t)l * NH + h) * NM + (o - 2 * NO);
            cpa4(vb + (uint32_t)(h * NP + o) * 4u, src);
        }
        if (tid < NOUT) {
            uint32_t bb = (uint32_t)__cvta_generic_to_shared(bsm + slot * NP);
            const float* src = (tid < NO) ? b_mu + (size_t)l * NO + tid
                : (tid < 2 * NO) ? b_sigma + (size_t)l * NO + (tid - NO)
                : b_pi + (size_t)l * NM + (tid - 2 * NO);
            cpa4(bb + (uint32_t)tid * 4u, src);
        }
    };

    prefetch_v(l0, 0); CP_COMMIT();
    if (l0 + 1 < l1) prefetch_v(l0 + 1, 1);
    CP_COMMIT();

    const float* gsp = g_S + ((size_t)g * NB + b0) * NH;

    for (int l = l0; l < l1; l++) {
        const int cur = (l - l0) & 1;
        CP_WAIT1();
        __syncthreads();   // Vcat[l] ready; prev step's reduce done with snap
        const float* vcur = vs + cur * NH * NP;
        const float* bcur = bsm + cur * NP;
        const int lp = (l > l0 ? l : l0 + 1) - 1;
        const float* pp = g_C + ((size_t)lp * NB + b0) * NH;

        float bacc[5][4];
#pragma unroll
        for (int t = 0; t < 5; t++) { bacc[t][0] = bacc[t][1] = bacc[t][2] = bacc[t][3] = 0.f; }

#pragma unroll
        for (int hs = 0; hs < 2; hs++) {
            // snapshot k-half hs: all 64 rows, h in [hs*256, hs*256+256)
#pragma unroll 8
            for (int j = 0; j < 32; j++) {
                int row = 2 * j + rpar;
                int h = hs * 256 + hoff;
                float v = gsp[row * NH + h];
                if (l > l0) v += pp[row * NH + h];
                snap[row * SNS + hoff] = tf32r(fmaxf(v, 0.f));
            }
            __syncthreads();
            // mma over this half: qw owns k-local [qw*64, qw*64+64)
            const float* ap = snap + (mrow0 + gid) * SNS + qw * 64 + tig;
#pragma unroll
            for (int s = 0; s < 8; s++) {
                uint32_t a[4];
                a[0] = __float_as_uint(ap[s * 8]);
                a[1] = __float_as_uint(ap[8 * SNS + s * 8]);
                a[2] = __float_as_uint(ap[s * 8 + 4]);
                a[3] = __float_as_uint(ap[8 * SNS + s * 8 + 4]);
                const float* vp = vcur + (hs * 256 + qw * 64 + s * 8 + tig) * NP + gid;
#pragma unroll
                for (int t = 0; t < 5; t++) {
                    uint32_t bb0 = tf32u(vp[t * 8]);
                    uint32_t bb1 = tf32u(vp[4 * NP + t * 8]);
                    mma8(bacc[t], a, bb0, bb1);
                }
            }
            __syncthreads();   // half fully consumed before snap reuse
        }

        // Vcat[l] fully consumed -> prefetch l+2 into this slot
        if (l + 2 < l1) prefetch_v(l + 2, cur);
        CP_COMMIT();

        // 4-way k-reduction through snap scratch
        if (qw != 0) {
            float* red = snap + (qw - 1) * (BT * NP);
#pragma unroll
            for (int t = 0; t < 5; t++) {
                int col = t * 8 + 2 * tig, row = mrow0 + gid;
                *(float2*)&red[row * NP + col]       = make_float2(bacc[t][0], bacc[t][1]);
                *(float2*)&red[(row + 8) * NP + col] = make_float2(bacc[t][2], bacc[t][3]);
            }
        }
        __syncthreads();
        if (qw == 0) {
#pragma unroll
            for (int t = 0; t < 5; t++) {
                int col = t * 8 + 2 * tig, row = mrow0 + gid;
                float v0 = bacc[t][0] + bcur[col];
                float v1 = bacc[t][1] + bcur[col + 1];
                float v2 = bacc[t][2] + bcur[col];
                float v3 = bacc[t][3] + bcur[col + 1];
#pragma unroll
                for (int kg = 0; kg < 3; kg++) {
                    const float* r0 = snap + kg * (BT * NP) + row * NP + col;
                    v0 += r0[0]; v1 += r0[1];
                    v2 += r0[8 * NP]; v3 += r0[8 * NP + 1];
                }
                size_t ob  = ((size_t)(b0 + row) * NL + l) * NOUT + col;
                size_t ob2 = ((size_t)(b0 + row + 8) * NL + l) * NOUT + col;
                if (col < NOUT)     { out[ob]     = v0; out[ob2]     = v2; }
                if (col + 1 < NOUT) { out[ob + 1] = v1; out[ob2 + 1] = v3; }
            }
        }
    }
}

// -------------------------------------------------------------------------
extern "C" void kernel_launch(void* const* d_in, const int* in_sizes, int n_in,
                              void* d_out, int out_size)
{
    const float* inputs  = (const float*)d_in[0];
    const float* z       = (const float*)d_in[1];
    const float* W_enc   = (const float*)d_in[2];
    const float* b_enc   = (const float*)d_in[3];
    const float* V_mu    = (const float*)d_in[4];
    const float* b_mu    = (const float*)d_in[5];
    const float* V_sigma = (const float*)d_in[6];
    const float* b_sigma = (const float*)d_in[7];
    const float* V_pi    = (const float*)d_in[8];
    const float* b_pi    = (const float*)d_in[9];
    float* out = (float*)d_out;

    const int SMEM_K1 = 2 * K1BUF * 4;                               // 188,928 B
    const int SMEM_K3 = (BT * SNS + 2 * NH * NP + 2 * NP) * 4;       // 230,720 B

    cudaFuncSetAttribute(k_chunksum, cudaFuncAttributeMaxDynamicSharedMemorySize, SMEM_K1);
    cudaFuncSetAttribute(k_main,     cudaFuncAttributeMaxDynamicSharedMemorySize, SMEM_K3);

    k_chunksum<<<dim3(NG, NB / BT), 512, SMEM_K1>>>(inputs, z, W_enc);
    k_scan<<<(NB * NH) / 512, 512>>>(b_enc);
    k_main<<<dim3(NG, NB / BT), 512, SMEM_K3>>>(
        V_mu, b_mu, V_sigma, b_sigma, V_pi, b_pi, out);
}